// round 14
// baseline (speedup 1.0000x reference)
#include <cuda_runtime.h>
#include <cuda_bf16.h>
#include <math.h>
#include <stdint.h>

// Problem constants
#define B_  2
#define S_  2048
#define D_  1024
#define H_  16
#define DK_ 64

// GEMM tiling (tf32): 128x64 tile, 256 threads, 2-stage, 3 CTAs/SM
#define BM 128
#define BN 64
#define BK 32
#define KDIM 1024
#define CHUNKS 32
#define RS 36                            // fp32 row stride (bank-conflict-free)
#define A_T (128 * RS * 4)               // 18432 B
#define B_T (64 * RS * 4)                // 9216 B
#define BUF (A_T + B_T)                  // 27648
#define GEMM_SMEM (2 * BUF)              // 55296

// Attention smem layout (64-key tiles, 2 CTAs/SM)
#define SK 72
#define QT_B (128 * SK * 2)
#define KT_B (64 * SK * 2)
#define QH_OFF 0
#define QL_OFF QT_B
#define KV_OFF(buf, t) (2 * QT_B + (buf) * 4 * KT_B + (t) * KT_B)
#define MS_OFF (2 * QT_B + 8 * KT_B)
#define FLAG_OFF (MS_OFF + 512)
#define ATTN_SMEM (FLAG_OFF + 128)

// Scratch (device globals)
__device__ __nv_bfloat16 g_qh[B_*S_*D_], g_ql[B_*S_*D_];
__device__ __nv_bfloat16 g_kh[B_*S_*D_], g_kl[B_*S_*D_];
__device__ __nv_bfloat16 g_vh[B_*S_*D_], g_vl[B_*S_*D_];
__device__ float g_ctx[B_*S_*D_];

// ===========================================================================
// Helpers
// ===========================================================================
__device__ __forceinline__ uint32_t smem_u32(const void* p) {
    uint32_t a;
    asm("{ .reg .u64 t; cvta.to.shared.u64 t, %1; cvt.u32.u64 %0, t; }"
        : "=r"(a) : "l"(p));
    return a;
}
__device__ __forceinline__ void cp16(uint32_t dst, const void* src) {
    asm volatile("cp.async.cg.shared.global [%0], [%1], 16;" :: "r"(dst), "l"(src));
}
__device__ __forceinline__ void cp4(uint32_t dst, const void* src) {
    asm volatile("cp.async.ca.shared.global [%0], [%1], 4;" :: "r"(dst), "l"(src));
}
__device__ __forceinline__ void ldmx4(uint32_t& r0, uint32_t& r1,
                                      uint32_t& r2, uint32_t& r3, uint32_t addr) {
    asm volatile("ldmatrix.sync.aligned.m8n8.x4.shared.b16 {%0,%1,%2,%3}, [%4];"
                 : "=r"(r0), "=r"(r1), "=r"(r2), "=r"(r3) : "r"(addr));
}
__device__ __forceinline__ void ldmx4t(uint32_t& r0, uint32_t& r1,
                                       uint32_t& r2, uint32_t& r3, uint32_t addr) {
    asm volatile("ldmatrix.sync.aligned.m8n8.x4.trans.shared.b16 {%0,%1,%2,%3}, [%4];"
                 : "=r"(r0), "=r"(r1), "=r"(r2), "=r"(r3) : "r"(addr));
}
__device__ __forceinline__ void mma16816(float* c, const uint32_t* a,
                                         uint32_t b0, uint32_t b1) {
    asm volatile(
        "mma.sync.aligned.m16n8k16.row.col.f32.bf16.bf16.f32 "
        "{%0,%1,%2,%3}, {%4,%5,%6,%7}, {%8,%9}, {%0,%1,%2,%3};"
        : "+f"(c[0]), "+f"(c[1]), "+f"(c[2]), "+f"(c[3])
        : "r"(a[0]), "r"(a[1]), "r"(a[2]), "r"(a[3]), "r"(b0), "r"(b1));
}
__device__ __forceinline__ void mma_tf32(float* c, const uint32_t* a,
                                         uint32_t b0, uint32_t b1) {
    asm volatile(
        "mma.sync.aligned.m16n8k8.row.col.f32.tf32.tf32.f32 "
        "{%0,%1,%2,%3}, {%4,%5,%6,%7}, {%8,%9}, {%0,%1,%2,%3};"
        : "+f"(c[0]), "+f"(c[1]), "+f"(c[2]), "+f"(c[3])
        : "r"(a[0]), "r"(a[1]), "r"(a[2]), "r"(a[3]), "r"(b0), "r"(b1));
}
__device__ __forceinline__ uint32_t cvt2bf(float hi_elem, float lo_elem) {
    uint32_t r;
    asm("cvt.rn.bf16x2.f32 %0, %1, %2;" : "=r"(r) : "f"(hi_elem), "f"(lo_elem));
    return r;
}
__device__ __forceinline__ float bflo(uint32_t p) { return __uint_as_float(p << 16); }
__device__ __forceinline__ float bfhi(uint32_t p) { return __uint_as_float(p & 0xFFFF0000u); }
__device__ __forceinline__ float ex2f(float x) {
    float y; asm("ex2.approx.f32 %0, %1;" : "=f"(y) : "f"(x)); return y;
}

// ===========================================================================
// TF32 GEMM (NT + bias, optional output scale): 128x64 tiles, 256 thr,
// 3 CTAs/SM target, warp tile 32x32, 2-stage cp.async, single barrier.
// Raw fp32 operands (hardware tf32 truncation).
// SPLIT -> bf16 hi/lo outputs; else fp32.
// ===========================================================================
template<bool SPLIT>
__global__ __launch_bounds__(256, 3) void gemm_tf32(
    const float* __restrict__ a0, const float* __restrict__ w0,
    const float* __restrict__ bias0,
    const float* __restrict__ a1, const float* __restrict__ w1,
    const float* __restrict__ bias1,
    const float* __restrict__ a2, const float* __restrict__ w2,
    const float* __restrict__ bias2,
    float s0, float s1, float s2,
    float* __restrict__ Cf,
    __nv_bfloat16* __restrict__ C0h, __nv_bfloat16* __restrict__ C0l,
    __nv_bfloat16* __restrict__ C1h, __nv_bfloat16* __restrict__ C1l,
    __nv_bfloat16* __restrict__ C2h, __nv_bfloat16* __restrict__ C2l)
{
    extern __shared__ char dynsm[];
    const uint32_t smb = smem_u32(dynsm);
    const int tid = threadIdx.x;
    const int l = tid & 31;
    const int wid = tid >> 5;
    const int wm = (wid & 3) * 32;
    const int wn = (wid >> 2) * 32;
    const int bm = blockIdx.y * BM;
    const int bn = blockIdx.x * BN;
    const int z = blockIdx.z;

    const float* A = (z == 0) ? a0 : (z == 1) ? a1 : a2;
    const float* W = (z == 0) ? w0 : (z == 1) ? w1 : w2;
    const float* bias = (z == 0) ? bias0 : (z == 1) ? bias1 : bias2;
    const float osc = (z == 0) ? s0 : (z == 1) ? s1 : s2;
    __nv_bfloat16* Chi = (z == 0) ? C0h : (z == 1) ? C1h : C2h;
    __nv_bfloat16* Clo = (z == 0) ? C0l : (z == 1) ? C1l : C2l;

    float acc[2][4][4];
    #pragma unroll
    for (int mi = 0; mi < 2; mi++)
        #pragma unroll
        for (int nj = 0; nj < 4; nj++)
            #pragma unroll
            for (int q = 0; q < 4; q++) acc[mi][nj][q] = 0.0f;

    auto issue = [&](int c, int buf) {
        const int kk = c * BK;
        const uint32_t base = smb + buf * BUF;
        #pragma unroll
        for (int i = 0; i < 4; i++) {           // A: 1024 cp16 ops
            int idx = tid + i * 256;
            int row = idx >> 3, s4 = (idx & 7) * 4;
            cp16(base + (uint32_t)(row * RS + s4) * 4,
                 A + (size_t)(bm + row) * KDIM + kk + s4);
        }
        #pragma unroll
        for (int i = 0; i < 2; i++) {           // B: 512 cp16 ops
            int idx = tid + i * 256;
            int row = idx >> 3, s4 = (idx & 7) * 4;
            cp16(base + A_T + (uint32_t)(row * RS + s4) * 4,
                 W + (size_t)(bn + row) * KDIM + kk + s4);
        }
        asm volatile("cp.async.commit_group;" ::: "memory");
    };

    // Quadrant row/col for tf32 fragment via ldmatrix-b16 trick
    const int qrow = (l & 7) + ((l >> 3) & 1) * 8;
    const int qcol = (l >> 4) * 4;

    auto compute = [&](int buf) {
        const uint32_t aB = smb + buf * BUF;
        const uint32_t bB = aB + A_T;
        #pragma unroll
        for (int k8 = 0; k8 < 4; k8++) {
            uint32_t a[2][4];
            #pragma unroll
            for (int mi = 0; mi < 2; mi++) {
                uint32_t addr = aB + (uint32_t)((wm + mi * 16 + qrow) * RS
                                                + k8 * 8 + qcol) * 4;
                ldmx4(a[mi][0], a[mi][1], a[mi][2], a[mi][3], addr);
            }
            uint32_t b[2][4];
            #pragma unroll
            for (int p = 0; p < 2; p++) {
                uint32_t addr = bB + (uint32_t)((wn + p * 16 + qrow) * RS
                                                + k8 * 8 + qcol) * 4;
                ldmx4(b[p][0], b[p][1], b[p][2], b[p][3], addr);
            }
            #pragma unroll
            for (int p = 0; p < 2; p++) {
                #pragma unroll
                for (int mi = 0; mi < 2; mi++) {
                    mma_tf32(acc[mi][2 * p],     a[mi], b[p][0], b[p][2]);
                    mma_tf32(acc[mi][2 * p + 1], a[mi], b[p][1], b[p][3]);
                }
            }
        }
    };

    issue(0, 0);
    for (int c = 0; c < CHUNKS; ++c) {
        asm volatile("cp.async.wait_group 0;" ::: "memory");
        __syncthreads();
        // Single-barrier 2-stage: buffer (c+1)&1 was last read in compute(c-1),
        // finished by all threads before the barrier above.
        if (c + 1 < CHUNKS) issue(c + 1, (c + 1) & 1);
        compute(c & 1);
    }

    #pragma unroll
    for (int mi = 0; mi < 2; mi++) {
        int r0 = bm + wm + mi * 16 + (l >> 2);
        #pragma unroll
        for (int nj = 0; nj < 4; nj++) {
            int col = bn + wn + nj * 8 + (l & 3) * 2;
            float2 bv = *(const float2*)&bias[col];
            float v0 = (acc[mi][nj][0] + bv.x) * osc;
            float v1 = (acc[mi][nj][1] + bv.y) * osc;
            float v2 = (acc[mi][nj][2] + bv.x) * osc;
            float v3 = (acc[mi][nj][3] + bv.y) * osc;
            if (SPLIT) {
                uint32_t ph = cvt2bf(v1, v0);
                uint32_t pl = cvt2bf(v1 - bfhi(ph), v0 - bflo(ph));
                *(uint32_t*)&Chi[(size_t)r0 * D_ + col] = ph;
                *(uint32_t*)&Clo[(size_t)r0 * D_ + col] = pl;
                ph = cvt2bf(v3, v2);
                pl = cvt2bf(v3 - bfhi(ph), v2 - bflo(ph));
                *(uint32_t*)&Chi[(size_t)(r0 + 8) * D_ + col] = ph;
                *(uint32_t*)&Clo[(size_t)(r0 + 8) * D_ + col] = pl;
            } else {
                *(float2*)&Cf[(size_t)r0 * D_ + col] = make_float2(v0, v1);
                *(float2*)&Cf[(size_t)(r0 + 8) * D_ + col] = make_float2(v2, v3);
            }
        }
    }
}

// ===========================================================================
// Tensor-core flash attention (bf16 hi/lo, exp2-domain softmax) — R12 version.
// ===========================================================================
__global__ __launch_bounds__(256, 2) void attn_mma(
    const __nv_bfloat16* __restrict__ qHi, const __nv_bfloat16* __restrict__ qLo,
    const __nv_bfloat16* __restrict__ kHi, const __nv_bfloat16* __restrict__ kLo,
    const __nv_bfloat16* __restrict__ vHi, const __nv_bfloat16* __restrict__ vLo,
    const int* __restrict__ mask,
    float* __restrict__ ctx)
{
    extern __shared__ char dynsm[];
    const uint32_t smb = smem_u32(dynsm);
    const int tid = threadIdx.x;
    const int w = tid >> 5, l = tid & 31;
    const int b = blockIdx.z, h = blockIdx.y;
    const int q0 = blockIdx.x * 128;
    const size_t bS = (size_t)b * S_;
    const int hd = h * DK_;

    // Per-tile all-ones flags
    {
        const int4* mp = (const int4*)(mask + b * S_);
        int4 a = mp[tid * 2];
        int4 c = mp[tid * 2 + 1];
        int allm = a.x & a.y & a.z & a.w & c.x & c.y & c.z & c.w;
        allm &= __shfl_xor_sync(0xffffffffu, allm, 1);
        allm &= __shfl_xor_sync(0xffffffffu, allm, 2);
        allm &= __shfl_xor_sync(0xffffffffu, allm, 4);
        if ((tid & 7) == 0)
            ((int*)(dynsm + FLAG_OFF))[tid >> 3] = allm;
    }

    auto load_q = [&](const __nv_bfloat16* g, uint32_t off) {
        #pragma unroll
        for (int t = 0; t < 4; t++) {
            int idx = tid + t * 256;
            int row = idx >> 3, seg = (idx & 7) * 8;
            cp16(smb + off + (uint32_t)(row * SK + seg) * 2,
                 g + (bS + q0 + row) * D_ + hd + seg);
        }
    };
    auto load_kv_tile = [&](const __nv_bfloat16* g, uint32_t off, int tok0) {
        #pragma unroll
        for (int t = 0; t < 2; t++) {
            int idx = tid + t * 256;
            int row = idx >> 3, seg = (idx & 7) * 8;
            cp16(smb + off + (uint32_t)(row * SK + seg) * 2,
                 g + (bS + tok0 + row) * D_ + hd + seg);
        }
    };
    auto load_kv = [&](int kt, int buf) {
        int tok0 = kt * 64;
        load_kv_tile(kHi, KV_OFF(buf, 0), tok0);
        load_kv_tile(kLo, KV_OFF(buf, 1), tok0);
        load_kv_tile(vHi, KV_OFF(buf, 2), tok0);
        load_kv_tile(vLo, KV_OFF(buf, 3), tok0);
        if (tid < 64) cp4(smb + MS_OFF + (uint32_t)(buf * 64 + tid) * 4,
                          mask + b * S_ + tok0 + tid);
    };

    load_q(qHi, QH_OFF);
    load_q(qLo, QL_OFF);
    load_kv(0, 0);
    asm volatile("cp.async.commit_group;" ::: "memory");

    float Oacc[8][4];
    #pragma unroll
    for (int nf = 0; nf < 8; nf++)
        #pragma unroll
        for (int q = 0; q < 4; q++) Oacc[nf][q] = 0.0f;
    float mrun0 = -1e30f, mrun1 = -1e30f, lrun0 = 0.0f, lrun1 = 0.0f;

    const uint32_t a_off = (uint32_t)((w * 16 + (l & 15)) * SK + ((l >> 4) << 3)) * 2;
    const int bmat = l >> 3, br8 = l & 7;

    for (int kt = 0; kt < 32; kt++) {
        const int buf = kt & 1;
        if (kt < 31) {
            load_kv(kt + 1, buf ^ 1);
            asm volatile("cp.async.commit_group;" ::: "memory");
            asm volatile("cp.async.wait_group 1;" ::: "memory");
        } else {
            asm volatile("cp.async.wait_group 0;" ::: "memory");
        }
        __syncthreads();

        const uint32_t KhB = smb + KV_OFF(buf, 0), KlB = smb + KV_OFF(buf, 1);
        const uint32_t VhB = smb + KV_OFF(buf, 2), VlB = smb + KV_OFF(buf, 3);

        float sacc[8][4];
        #pragma unroll
        for (int f = 0; f < 8; f++)
            #pragma unroll
            for (int q = 0; q < 4; q++) sacc[f][q] = 0.0f;

        #pragma unroll
        for (int kc = 0; kc < 4; kc++) {
            uint32_t aH[4], aL[4];
            ldmx4(aH[0], aH[1], aH[2], aH[3], smb + QH_OFF + a_off + kc * 32);
            ldmx4(aL[0], aL[1], aL[2], aL[3], smb + QL_OFF + a_off + kc * 32);
            #pragma unroll
            for (int np = 0; np < 4; np++) {
                uint32_t badr = (uint32_t)((np * 16 + ((bmat >> 1) << 3) + br8) * SK
                                           + kc * 16 + ((bmat & 1) << 3)) * 2;
                uint32_t bh0, bh1, bh2, bh3, bl0, bl1, bl2, bl3;
                ldmx4(bh0, bh1, bh2, bh3, KhB + badr);
                ldmx4(bl0, bl1, bl2, bl3, KlB + badr);
                mma16816(sacc[2 * np],     aH, bh0, bh1);
                mma16816(sacc[2 * np + 1], aH, bh2, bh3);
                mma16816(sacc[2 * np],     aH, bl0, bl1);
                mma16816(sacc[2 * np + 1], aH, bl2, bl3);
                mma16816(sacc[2 * np],     aL, bh0, bh1);
                mma16816(sacc[2 * np + 1], aL, bh2, bh3);
            }
        }

        const int allm = ((const int*)(dynsm + FLAG_OFF))[kt];
        float mx0 = -1e30f, mx1 = -1e30f;
        if (allm) {
            #pragma unroll
            for (int f = 0; f < 8; f++) {
                mx0 = fmaxf(mx0, fmaxf(sacc[f][0], sacc[f][1]));
                mx1 = fmaxf(mx1, fmaxf(sacc[f][2], sacc[f][3]));
            }
        } else {
            const int* ms = (const int*)(dynsm + MS_OFF + buf * 256);
            #pragma unroll
            for (int f = 0; f < 8; f++) {
                int c0 = f * 8 + (l & 3) * 2;
                int mk0 = ms[c0], mk1 = ms[c0 + 1];
                float t0 = mk0 ? sacc[f][0] : -1e30f;
                float t1 = mk1 ? sacc[f][1] : -1e30f;
                float t2 = mk0 ? sacc[f][2] : -1e30f;
                float t3 = mk1 ? sacc[f][3] : -1e30f;
                sacc[f][0] = t0; sacc[f][1] = t1; sacc[f][2] = t2; sacc[f][3] = t3;
                mx0 = fmaxf(mx0, fmaxf(t0, t1));
                mx1 = fmaxf(mx1, fmaxf(t2, t3));
            }
        }
        mx0 = fmaxf(mx0, __shfl_xor_sync(0xffffffffu, mx0, 1));
        mx0 = fmaxf(mx0, __shfl_xor_sync(0xffffffffu, mx0, 2));
        mx1 = fmaxf(mx1, __shfl_xor_sync(0xffffffffu, mx1, 1));
        mx1 = fmaxf(mx1, __shfl_xor_sync(0xffffffffu, mx1, 2));
        float mn0 = fmaxf(mrun0, mx0), mn1 = fmaxf(mrun1, mx1);
        float cor0 = ex2f(mrun0 - mn0), cor1 = ex2f(mrun1 - mn1);
        mrun0 = mn0; mrun1 = mn1;
        float sum0 = 0.0f, sum1 = 0.0f;
        #pragma unroll
        for (int f = 0; f < 8; f++) {
            float p0 = ex2f(sacc[f][0] - mn0);
            float p1 = ex2f(sacc[f][1] - mn0);
            float p2 = ex2f(sacc[f][2] - mn1);
            float p3 = ex2f(sacc[f][3] - mn1);
            sacc[f][0] = p0; sacc[f][1] = p1; sacc[f][2] = p2; sacc[f][3] = p3;
            sum0 += p0 + p1; sum1 += p2 + p3;
        }
        sum0 += __shfl_xor_sync(0xffffffffu, sum0, 1);
        sum0 += __shfl_xor_sync(0xffffffffu, sum0, 2);
        sum1 += __shfl_xor_sync(0xffffffffu, sum1, 1);
        sum1 += __shfl_xor_sync(0xffffffffu, sum1, 2);
        lrun0 = lrun0 * cor0 + sum0;
        lrun1 = lrun1 * cor1 + sum1;
        #pragma unroll
        for (int nf = 0; nf < 8; nf++) {
            Oacc[nf][0] *= cor0; Oacc[nf][1] *= cor0;
            Oacc[nf][2] *= cor1; Oacc[nf][3] *= cor1;
        }

        #pragma unroll
        for (int kc2 = 0; kc2 < 4; kc2++) {
            const float* f0 = sacc[2 * kc2];
            const float* f1 = sacc[2 * kc2 + 1];
            uint32_t aH2[4], aL2[4];
            aH2[0] = cvt2bf(f0[1], f0[0]);
            aH2[1] = cvt2bf(f0[3], f0[2]);
            aH2[2] = cvt2bf(f1[1], f1[0]);
            aH2[3] = cvt2bf(f1[3], f1[2]);
            aL2[0] = cvt2bf(f0[1] - bfhi(aH2[0]), f0[0] - bflo(aH2[0]));
            aL2[1] = cvt2bf(f0[3] - bfhi(aH2[1]), f0[2] - bflo(aH2[1]));
            aL2[2] = cvt2bf(f1[1] - bfhi(aH2[2]), f1[0] - bflo(aH2[2]));
            aL2[3] = cvt2bf(f1[3] - bfhi(aH2[3]), f1[2] - bflo(aH2[3]));
            #pragma unroll
            for (int nf = 0; nf < 4; nf++) {
                uint32_t vadr = (uint32_t)((kc2 * 16 + (l & 15)) * SK
                                           + nf * 16 + ((l >> 4) << 3)) * 2;
                uint32_t vh0, vh1, vh2, vh3, vl0, vl1, vl2, vl3;
                ldmx4t(vh0, vh1, vh2, vh3, VhB + vadr);
                ldmx4t(vl0, vl1, vl2, vl3, VlB + vadr);
                mma16816(Oacc[2 * nf],     aH2, vh0, vh1);
                mma16816(Oacc[2 * nf + 1], aH2, vh2, vh3);
                mma16816(Oacc[2 * nf],     aH2, vl0, vl1);
                mma16816(Oacc[2 * nf + 1], aH2, vl2, vl3);
                mma16816(Oacc[2 * nf],     aL2, vh0, vh1);
                mma16816(Oacc[2 * nf + 1], aL2, vh2, vh3);
            }
        }
        __syncthreads();
    }

    // Epilogue: normalize, write fp32 ctx
    const float inv0 = 1.0f / lrun0;
    const float inv1 = 1.0f / lrun1;
    const int r0 = q0 + w * 16 + (l >> 2);
    #pragma unroll
    for (int nf = 0; nf < 8; nf++) {
        int col = hd + nf * 8 + (l & 3) * 2;
        float2 o0, o1;
        o0.x = Oacc[nf][0] * inv0;
        o0.y = Oacc[nf][1] * inv0;
        o1.x = Oacc[nf][2] * inv1;
        o1.y = Oacc[nf][3] * inv1;
        *(float2*)&ctx[(bS + r0) * D_ + col] = o0;
        *(float2*)&ctx[(bS + r0 + 8) * D_ + col] = o1;
    }
}

// ---------------------------------------------------------------------------
extern "C" void kernel_launch(void* const* d_in, const int* in_sizes, int n_in,
                              void* d_out, int out_size)
{
    (void)in_sizes; (void)n_in; (void)out_size;
    const float* query = (const float*)d_in[0];
    const float* key   = (const float*)d_in[1];
    const float* value = (const float*)d_in[2];
    const int*   mask  = (const int*)d_in[3];
    const float* Wq = (const float*)d_in[4];
    const float* bq = (const float*)d_in[5];
    const float* Wk = (const float*)d_in[6];
    const float* bk = (const float*)d_in[7];
    const float* Wv = (const float*)d_in[8];
    const float* bv = (const float*)d_in[9];
    const float* Wo = (const float*)d_in[10];
    const float* bo = (const float*)d_in[11];
    float* out = (float*)d_out;

    __nv_bfloat16 *qh, *ql, *kh, *kl, *vh, *vl;
    float *ctx;
    cudaGetSymbolAddress((void**)&qh, g_qh);   cudaGetSymbolAddress((void**)&ql, g_ql);
    cudaGetSymbolAddress((void**)&kh, g_kh);   cudaGetSymbolAddress((void**)&kl, g_kl);
    cudaGetSymbolAddress((void**)&vh, g_vh);   cudaGetSymbolAddress((void**)&vl, g_vl);
    cudaGetSymbolAddress((void**)&ctx, g_ctx);

    const float SC2 = 0.18033688011112042f;   // 0.125 * log2(e)

    cudaFuncSetAttribute(gemm_tf32<true>, cudaFuncAttributeMaxDynamicSharedMemorySize,
                         GEMM_SMEM);
    cudaFuncSetAttribute(gemm_tf32<false>, cudaFuncAttributeMaxDynamicSharedMemorySize,
                         GEMM_SMEM);
    cudaFuncSetAttribute(attn_mma, cudaFuncAttributeMaxDynamicSharedMemorySize,
                         ATTN_SMEM);

    // Fused Q/K/V projections (tf32 single-pass, raw-bit operands);
    // Q pre-scaled into exp2 domain
    dim3 ggrid(D_ / BN, (B_ * S_) / BM, 3);   // (16, 32, 3)
    gemm_tf32<true><<<ggrid, 256, GEMM_SMEM>>>(
        query, Wq, bq,
        key,   Wk, bk,
        value, Wv, bv,
        SC2, 1.0f, 1.0f,
        nullptr, qh, ql, kh, kl, vh, vl);

    // Attention (bf16 hi/lo) -> fp32 ctx
    dim3 agrid(S_ / 128, H_, B_);
    attn_mma<<<agrid, 256, ATTN_SMEM>>>(qh, ql, kh, kl, vh, vl, mask, ctx);

    // Output projection (tf32 single-pass, fp32 out)
    dim3 ogrid(D_ / BN, (B_ * S_) / BM, 1);   // (16, 32, 1)
    gemm_tf32<false><<<ogrid, 256, GEMM_SMEM>>>(
        ctx, Wo, bo,
        ctx, Wo, bo,
        ctx, Wo, bo,
        1.0f, 1.0f, 1.0f,
        out, nullptr, nullptr, nullptr, nullptr, nullptr, nullptr);
}

// round 15
// speedup vs baseline: 1.0521x; 1.0521x over previous
#include <cuda_runtime.h>
#include <cuda_bf16.h>
#include <math.h>
#include <stdint.h>

// Problem constants
#define B_  2
#define S_  2048
#define D_  1024
#define H_  16
#define DK_ 64

// GEMM tiling (tf32): 128x128 tile, 256 threads, 3-stage, 2 CTAs/SM (R12)
#define BM 128
#define BN 128
#define BK 32
#define KDIM 1024
#define CHUNKS 32
#define RS 36                            // fp32 row stride (bank-conflict-free)
#define A_T (128 * RS * 4)               // 18432 B
#define B_T (128 * RS * 4)
#define BUF (A_T + B_T)                  // 36864
#define GEMM_SMEM (3 * BUF)              // 110592

// Attention smem: Q/K fp32 (tf32 QK), V bf16 hi/lo (3-pass PV), 2 CTAs/SM
#define RSF 68                           // fp32 row stride (68 mod 32 == 4)
#define SK 72                            // bf16 row stride
#define QF_BYTES (128 * RSF * 4)         // 34816
#define KF_BYTES (64 * RSF * 4)          // 17408
#define VT_B (64 * SK * 2)               // 9216
#define QF_OFF 0
#define KF_OFF(buf) (QF_BYTES + (buf) * KF_BYTES)
#define VH_OFF(buf) (QF_BYTES + 2 * KF_BYTES + (buf) * 2 * VT_B)
#define VL_OFF(buf) (VH_OFF(buf) + VT_B)
#define MS_OFF (QF_BYTES + 2 * KF_BYTES + 4 * VT_B)   // 106496
#define FLAG_OFF (MS_OFF + 512)                        // 107008
#define ATTN_SMEM (FLAG_OFF + 128)                     // 107136

// Scratch (device globals)
__device__ float g_qf[B_*S_*D_], g_kf[B_*S_*D_];
__device__ __nv_bfloat16 g_vh[B_*S_*D_], g_vl[B_*S_*D_];
__device__ float g_ctx[B_*S_*D_];

// ===========================================================================
// Helpers
// ===========================================================================
__device__ __forceinline__ uint32_t smem_u32(const void* p) {
    uint32_t a;
    asm("{ .reg .u64 t; cvta.to.shared.u64 t, %1; cvt.u32.u64 %0, t; }"
        : "=r"(a) : "l"(p));
    return a;
}
__device__ __forceinline__ void cp16(uint32_t dst, const void* src) {
    asm volatile("cp.async.cg.shared.global [%0], [%1], 16;" :: "r"(dst), "l"(src));
}
__device__ __forceinline__ void cp4(uint32_t dst, const void* src) {
    asm volatile("cp.async.ca.shared.global [%0], [%1], 4;" :: "r"(dst), "l"(src));
}
__device__ __forceinline__ void ldmx4(uint32_t& r0, uint32_t& r1,
                                      uint32_t& r2, uint32_t& r3, uint32_t addr) {
    asm volatile("ldmatrix.sync.aligned.m8n8.x4.shared.b16 {%0,%1,%2,%3}, [%4];"
                 : "=r"(r0), "=r"(r1), "=r"(r2), "=r"(r3) : "r"(addr));
}
__device__ __forceinline__ void ldmx4t(uint32_t& r0, uint32_t& r1,
                                       uint32_t& r2, uint32_t& r3, uint32_t addr) {
    asm volatile("ldmatrix.sync.aligned.m8n8.x4.trans.shared.b16 {%0,%1,%2,%3}, [%4];"
                 : "=r"(r0), "=r"(r1), "=r"(r2), "=r"(r3) : "r"(addr));
}
__device__ __forceinline__ void mma16816(float* c, const uint32_t* a,
                                         uint32_t b0, uint32_t b1) {
    asm volatile(
        "mma.sync.aligned.m16n8k16.row.col.f32.bf16.bf16.f32 "
        "{%0,%1,%2,%3}, {%4,%5,%6,%7}, {%8,%9}, {%0,%1,%2,%3};"
        : "+f"(c[0]), "+f"(c[1]), "+f"(c[2]), "+f"(c[3])
        : "r"(a[0]), "r"(a[1]), "r"(a[2]), "r"(a[3]), "r"(b0), "r"(b1));
}
__device__ __forceinline__ void mma_tf32(float* c, const uint32_t* a,
                                         uint32_t b0, uint32_t b1) {
    asm volatile(
        "mma.sync.aligned.m16n8k8.row.col.f32.tf32.tf32.f32 "
        "{%0,%1,%2,%3}, {%4,%5,%6,%7}, {%8,%9}, {%0,%1,%2,%3};"
        : "+f"(c[0]), "+f"(c[1]), "+f"(c[2]), "+f"(c[3])
        : "r"(a[0]), "r"(a[1]), "r"(a[2]), "r"(a[3]), "r"(b0), "r"(b1));
}
__device__ __forceinline__ uint32_t cvt2bf(float hi_elem, float lo_elem) {
    uint32_t r;
    asm("cvt.rn.bf16x2.f32 %0, %1, %2;" : "=r"(r) : "f"(hi_elem), "f"(lo_elem));
    return r;
}
__device__ __forceinline__ float bflo(uint32_t p) { return __uint_as_float(p << 16); }
__device__ __forceinline__ float bfhi(uint32_t p) { return __uint_as_float(p & 0xFFFF0000u); }
__device__ __forceinline__ float ex2f(float x) {
    float y; asm("ex2.approx.f32 %0, %1;" : "=f"(y) : "f"(x)); return y;
}

// ===========================================================================
// TF32 GEMM (NT + bias + scale): 128x128, 256 thr, 3-stage, 2 CTAs/SM (R12).
// Raw fp32 operands (hardware tf32 truncation).
// z==2 -> bf16 hi/lo split output; z==0/1 -> fp32 output.
// ===========================================================================
__global__ __launch_bounds__(256, 2) void gemm_tf32(
    const float* __restrict__ a0, const float* __restrict__ w0,
    const float* __restrict__ bias0,
    const float* __restrict__ a1, const float* __restrict__ w1,
    const float* __restrict__ bias1,
    const float* __restrict__ a2, const float* __restrict__ w2,
    const float* __restrict__ bias2,
    float s0, float s1, float s2,
    float* __restrict__ F0, float* __restrict__ F1,
    __nv_bfloat16* __restrict__ C2h, __nv_bfloat16* __restrict__ C2l)
{
    extern __shared__ char dynsm[];
    const uint32_t smb = smem_u32(dynsm);
    const int tid = threadIdx.x;
    const int l = tid & 31;
    const int wid = tid >> 5;
    const int wm = (wid & 3) * 32;
    const int wn = (wid >> 2) * 64;
    const int bm = blockIdx.y * BM;
    const int bn = blockIdx.x * BN;
    const int z = blockIdx.z;

    const float* A = (z == 0) ? a0 : (z == 1) ? a1 : a2;
    const float* W = (z == 0) ? w0 : (z == 1) ? w1 : w2;
    const float* bias = (z == 0) ? bias0 : (z == 1) ? bias1 : bias2;
    const float osc = (z == 0) ? s0 : (z == 1) ? s1 : s2;
    float* Fo = (z == 0) ? F0 : F1;

    float acc[2][8][4];
    #pragma unroll
    for (int mi = 0; mi < 2; mi++)
        #pragma unroll
        for (int nj = 0; nj < 8; nj++)
            #pragma unroll
            for (int q = 0; q < 4; q++) acc[mi][nj][q] = 0.0f;

    auto issue = [&](int c, int buf) {
        const int kk = c * BK;
        const uint32_t base = smb + buf * BUF;
        #pragma unroll
        for (int i = 0; i < 4; i++) {
            int idx = tid + i * 256;
            int row = idx >> 3, s4 = (idx & 7) * 4;
            uint32_t off = (uint32_t)(row * RS + s4) * 4;
            cp16(base + off,       A + (size_t)(bm + row) * KDIM + kk + s4);
            cp16(base + A_T + off, W + (size_t)(bn + row) * KDIM + kk + s4);
        }
        asm volatile("cp.async.commit_group;" ::: "memory");
    };

    const int qrow = (l & 7) + ((l >> 3) & 1) * 8;
    const int qcol = (l >> 4) * 4;

    auto compute = [&](int buf) {
        const uint32_t aB = smb + buf * BUF;
        const uint32_t bB = aB + A_T;
        #pragma unroll
        for (int k8 = 0; k8 < 4; k8++) {
            uint32_t a[2][4];
            #pragma unroll
            for (int mi = 0; mi < 2; mi++) {
                uint32_t addr = aB + (uint32_t)((wm + mi * 16 + qrow) * RS
                                                + k8 * 8 + qcol) * 4;
                ldmx4(a[mi][0], a[mi][1], a[mi][2], a[mi][3], addr);
            }
            uint32_t b[4][4];
            #pragma unroll
            for (int p = 0; p < 4; p++) {
                uint32_t addr = bB + (uint32_t)((wn + p * 16 + qrow) * RS
                                                + k8 * 8 + qcol) * 4;
                ldmx4(b[p][0], b[p][1], b[p][2], b[p][3], addr);
            }
            #pragma unroll
            for (int p = 0; p < 4; p++) {
                #pragma unroll
                for (int mi = 0; mi < 2; mi++) {
                    mma_tf32(acc[mi][2 * p],     a[mi], b[p][0], b[p][2]);
                    mma_tf32(acc[mi][2 * p + 1], a[mi], b[p][1], b[p][3]);
                }
            }
        }
    };

    issue(0, 0);
    issue(1, 1);
    for (int c = 0; c < CHUNKS; ++c) {
        if (c + 1 < CHUNKS) {
            asm volatile("cp.async.wait_group 1;" ::: "memory");
        } else {
            asm volatile("cp.async.wait_group 0;" ::: "memory");
        }
        __syncthreads();
        if (c + 2 < CHUNKS) issue(c + 2, (c + 2) % 3);
        compute(c % 3);
    }

    #pragma unroll
    for (int mi = 0; mi < 2; mi++) {
        int r0 = bm + wm + mi * 16 + (l >> 2);
        #pragma unroll
        for (int nj = 0; nj < 8; nj++) {
            int col = bn + wn + nj * 8 + (l & 3) * 2;
            float2 bv = *(const float2*)&bias[col];
            float v0 = (acc[mi][nj][0] + bv.x) * osc;
            float v1 = (acc[mi][nj][1] + bv.y) * osc;
            float v2 = (acc[mi][nj][2] + bv.x) * osc;
            float v3 = (acc[mi][nj][3] + bv.y) * osc;
            if (z == 2) {
                uint32_t ph = cvt2bf(v1, v0);
                uint32_t pl = cvt2bf(v1 - bfhi(ph), v0 - bflo(ph));
                *(uint32_t*)&C2h[(size_t)r0 * D_ + col] = ph;
                *(uint32_t*)&C2l[(size_t)r0 * D_ + col] = pl;
                ph = cvt2bf(v3, v2);
                pl = cvt2bf(v3 - bfhi(ph), v2 - bflo(ph));
                *(uint32_t*)&C2h[(size_t)(r0 + 8) * D_ + col] = ph;
                *(uint32_t*)&C2l[(size_t)(r0 + 8) * D_ + col] = pl;
            } else {
                *(float2*)&Fo[(size_t)r0 * D_ + col] = make_float2(v0, v1);
                *(float2*)&Fo[(size_t)(r0 + 8) * D_ + col] = make_float2(v2, v3);
            }
        }
    }
}

// ===========================================================================
// Flash attention: tf32 single-pass QK (fp32 Q/K in smem, quadrant ldmatrix),
// bf16 hi/lo 3-pass PV, exp2-domain softmax, 64-key tiles, 2 CTAs/SM.
// ===========================================================================
__global__ __launch_bounds__(256, 2) void attn_mma(
    const float* __restrict__ qF, const float* __restrict__ kF,
    const __nv_bfloat16* __restrict__ vHi, const __nv_bfloat16* __restrict__ vLo,
    const int* __restrict__ mask,
    float* __restrict__ ctx)
{
    extern __shared__ char dynsm[];
    const uint32_t smb = smem_u32(dynsm);
    const int tid = threadIdx.x;
    const int w = tid >> 5, l = tid & 31;
    const int b = blockIdx.z, h = blockIdx.y;
    const int q0 = blockIdx.x * 128;
    const size_t bS = (size_t)b * S_;
    const int hd = h * DK_;

    // Per-tile all-ones mask flags
    {
        const int4* mp = (const int4*)(mask + b * S_);
        int4 a = mp[tid * 2];
        int4 c = mp[tid * 2 + 1];
        int allm = a.x & a.y & a.z & a.w & c.x & c.y & c.z & c.w;
        allm &= __shfl_xor_sync(0xffffffffu, allm, 1);
        allm &= __shfl_xor_sync(0xffffffffu, allm, 2);
        allm &= __shfl_xor_sync(0xffffffffu, allm, 4);
        if ((tid & 7) == 0)
            ((int*)(dynsm + FLAG_OFF))[tid >> 3] = allm;
    }

    // Q fp32 tile load: 128 rows x 64 fp32
    {
        #pragma unroll
        for (int t = 0; t < 8; t++) {
            int idx = tid + t * 256;           // 0..2047
            int row = idx >> 4, seg = (idx & 15) * 4;
            cp16(smb + QF_OFF + (uint32_t)(row * RSF + seg) * 4,
                 qF + (bS + q0 + row) * D_ + hd + seg);
        }
    }
    auto load_kv = [&](int kt, int buf) {
        int tok0 = kt * 64;
        // K fp32: 64 rows x 64 fp32
        #pragma unroll
        for (int t = 0; t < 4; t++) {
            int idx = tid + t * 256;           // 0..1023
            int row = idx >> 4, seg = (idx & 15) * 4;
            cp16(smb + KF_OFF(buf) + (uint32_t)(row * RSF + seg) * 4,
                 kF + (bS + tok0 + row) * D_ + hd + seg);
        }
        // V bf16 hi/lo
        #pragma unroll
        for (int t = 0; t < 2; t++) {
            int idx = tid + t * 256;
            int row = idx >> 3, seg = (idx & 7) * 8;
            uint32_t off = (uint32_t)(row * SK + seg) * 2;
            cp16(smb + VH_OFF(buf) + off, vHi + (bS + tok0 + row) * D_ + hd + seg);
            cp16(smb + VL_OFF(buf) + off, vLo + (bS + tok0 + row) * D_ + hd + seg);
        }
        if (tid < 64) cp4(smb + MS_OFF + (uint32_t)(buf * 64 + tid) * 4,
                          mask + b * S_ + tok0 + tid);
    };

    load_kv(0, 0);
    asm volatile("cp.async.commit_group;" ::: "memory");

    float Oacc[8][4];
    #pragma unroll
    for (int nf = 0; nf < 8; nf++)
        #pragma unroll
        for (int q = 0; q < 4; q++) Oacc[nf][q] = 0.0f;
    float mrun0 = -1e30f, mrun1 = -1e30f, lrun0 = 0.0f, lrun1 = 0.0f;

    const int qrow = (l & 7) + ((l >> 3) & 1) * 8;
    const int qcol = (l >> 4) * 4;

    for (int kt = 0; kt < 32; kt++) {
        const int buf = kt & 1;
        if (kt < 31) {
            load_kv(kt + 1, buf ^ 1);
            asm volatile("cp.async.commit_group;" ::: "memory");
            asm volatile("cp.async.wait_group 1;" ::: "memory");
        } else {
            asm volatile("cp.async.wait_group 0;" ::: "memory");
        }
        __syncthreads();

        const uint32_t KfB = smb + KF_OFF(buf);
        const uint32_t VhB = smb + VH_OFF(buf), VlB = smb + VL_OFF(buf);

        float sacc[8][4];
        #pragma unroll
        for (int f = 0; f < 8; f++)
            #pragma unroll
            for (int q = 0; q < 4; q++) sacc[f][q] = 0.0f;

        // ---- S = Q K^T: single-pass tf32 (scores in exp2 domain) ----
        #pragma unroll
        for (int k8 = 0; k8 < 8; k8++) {
            uint32_t a[4];
            uint32_t aaddr = smb + QF_OFF + (uint32_t)((w * 16 + qrow) * RSF
                                                       + k8 * 8 + qcol) * 4;
            ldmx4(a[0], a[1], a[2], a[3], aaddr);
            #pragma unroll
            for (int p = 0; p < 4; p++) {
                uint32_t baddr = KfB + (uint32_t)((p * 16 + qrow) * RSF
                                                  + k8 * 8 + qcol) * 4;
                uint32_t b0, b1, b2, b3;
                ldmx4(b0, b1, b2, b3, baddr);
                mma_tf32(sacc[2 * p],     a, b0, b2);
                mma_tf32(sacc[2 * p + 1], a, b1, b3);
            }
        }

        // ---- mask (flagged fast path) + online softmax (exp2 domain) ----
        const int allm = ((const int*)(dynsm + FLAG_OFF))[kt];
        float mx0 = -1e30f, mx1 = -1e30f;
        if (allm) {
            #pragma unroll
            for (int f = 0; f < 8; f++) {
                mx0 = fmaxf(mx0, fmaxf(sacc[f][0], sacc[f][1]));
                mx1 = fmaxf(mx1, fmaxf(sacc[f][2], sacc[f][3]));
            }
        } else {
            const int* ms = (const int*)(dynsm + MS_OFF + buf * 256);
            #pragma unroll
            for (int f = 0; f < 8; f++) {
                int c0 = f * 8 + (l & 3) * 2;
                int mk0 = ms[c0], mk1 = ms[c0 + 1];
                float t0 = mk0 ? sacc[f][0] : -1e30f;
                float t1 = mk1 ? sacc[f][1] : -1e30f;
                float t2 = mk0 ? sacc[f][2] : -1e30f;
                float t3 = mk1 ? sacc[f][3] : -1e30f;
                sacc[f][0] = t0; sacc[f][1] = t1; sacc[f][2] = t2; sacc[f][3] = t3;
                mx0 = fmaxf(mx0, fmaxf(t0, t1));
                mx1 = fmaxf(mx1, fmaxf(t2, t3));
            }
        }
        mx0 = fmaxf(mx0, __shfl_xor_sync(0xffffffffu, mx0, 1));
        mx0 = fmaxf(mx0, __shfl_xor_sync(0xffffffffu, mx0, 2));
        mx1 = fmaxf(mx1, __shfl_xor_sync(0xffffffffu, mx1, 1));
        mx1 = fmaxf(mx1, __shfl_xor_sync(0xffffffffu, mx1, 2));
        float mn0 = fmaxf(mrun0, mx0), mn1 = fmaxf(mrun1, mx1);
        float cor0 = ex2f(mrun0 - mn0), cor1 = ex2f(mrun1 - mn1);
        mrun0 = mn0; mrun1 = mn1;
        float sum0 = 0.0f, sum1 = 0.0f;
        #pragma unroll
        for (int f = 0; f < 8; f++) {
            float p0 = ex2f(sacc[f][0] - mn0);
            float p1 = ex2f(sacc[f][1] - mn0);
            float p2 = ex2f(sacc[f][2] - mn1);
            float p3 = ex2f(sacc[f][3] - mn1);
            sacc[f][0] = p0; sacc[f][1] = p1; sacc[f][2] = p2; sacc[f][3] = p3;
            sum0 += p0 + p1; sum1 += p2 + p3;
        }
        sum0 += __shfl_xor_sync(0xffffffffu, sum0, 1);
        sum0 += __shfl_xor_sync(0xffffffffu, sum0, 2);
        sum1 += __shfl_xor_sync(0xffffffffu, sum1, 1);
        sum1 += __shfl_xor_sync(0xffffffffu, sum1, 2);
        lrun0 = lrun0 * cor0 + sum0;
        lrun1 = lrun1 * cor1 + sum1;
        #pragma unroll
        for (int nf = 0; nf < 8; nf++) {
            Oacc[nf][0] *= cor0; Oacc[nf][1] *= cor0;
            Oacc[nf][2] *= cor1; Oacc[nf][3] *= cor1;
        }

        // ---- O += P V (3-pass bf16 hi/lo) ----
        #pragma unroll
        for (int kc2 = 0; kc2 < 4; kc2++) {
            const float* f0 = sacc[2 * kc2];
            const float* f1 = sacc[2 * kc2 + 1];
            uint32_t aH2[4], aL2[4];
            aH2[0] = cvt2bf(f0[1], f0[0]);
            aH2[1] = cvt2bf(f0[3], f0[2]);
            aH2[2] = cvt2bf(f1[1], f1[0]);
            aH2[3] = cvt2bf(f1[3], f1[2]);
            aL2[0] = cvt2bf(f0[1] - bfhi(aH2[0]), f0[0] - bflo(aH2[0]));
            aL2[1] = cvt2bf(f0[3] - bfhi(aH2[1]), f0[2] - bflo(aH2[1]));
            aL2[2] = cvt2bf(f1[1] - bfhi(aH2[2]), f1[0] - bflo(aH2[2]));
            aL2[3] = cvt2bf(f1[3] - bfhi(aH2[3]), f1[2] - bflo(aH2[3]));
            #pragma unroll
            for (int nf = 0; nf < 4; nf++) {
                uint32_t vadr = (uint32_t)((kc2 * 16 + (l & 15)) * SK
                                           + nf * 16 + ((l >> 4) << 3)) * 2;
                uint32_t vh0, vh1, vh2, vh3, vl0, vl1, vl2, vl3;
                ldmx4t(vh0, vh1, vh2, vh3, VhB + vadr);
                ldmx4t(vl0, vl1, vl2, vl3, VlB + vadr);
                mma16816(Oacc[2 * nf],     aH2, vh0, vh1);
                mma16816(Oacc[2 * nf + 1], aH2, vh2, vh3);
                mma16816(Oacc[2 * nf],     aH2, vl0, vl1);
                mma16816(Oacc[2 * nf + 1], aH2, vl2, vl3);
                mma16816(Oacc[2 * nf],     aL2, vh0, vh1);
                mma16816(Oacc[2 * nf + 1], aL2, vh2, vh3);
            }
        }
        __syncthreads();
    }

    // Epilogue: normalize, write fp32 ctx
    const float inv0 = 1.0f / lrun0;
    const float inv1 = 1.0f / lrun1;
    const int r0 = q0 + w * 16 + (l >> 2);
    #pragma unroll
    for (int nf = 0; nf < 8; nf++) {
        int col = hd + nf * 8 + (l & 3) * 2;
        float2 o0, o1;
        o0.x = Oacc[nf][0] * inv0;
        o0.y = Oacc[nf][1] * inv0;
        o1.x = Oacc[nf][2] * inv1;
        o1.y = Oacc[nf][3] * inv1;
        *(float2*)&ctx[(bS + r0) * D_ + col] = o0;
        *(float2*)&ctx[(bS + r0 + 8) * D_ + col] = o1;
    }
}

// ---------------------------------------------------------------------------
extern "C" void kernel_launch(void* const* d_in, const int* in_sizes, int n_in,
                              void* d_out, int out_size)
{
    (void)in_sizes; (void)n_in; (void)out_size;
    const float* query = (const float*)d_in[0];
    const float* key   = (const float*)d_in[1];
    const float* value = (const float*)d_in[2];
    const int*   mask  = (const int*)d_in[3];
    const float* Wq = (const float*)d_in[4];
    const float* bq = (const float*)d_in[5];
    const float* Wk = (const float*)d_in[6];
    const float* bk = (const float*)d_in[7];
    const float* Wv = (const float*)d_in[8];
    const float* bv = (const float*)d_in[9];
    const float* Wo = (const float*)d_in[10];
    const float* bo = (const float*)d_in[11];
    float* out = (float*)d_out;

    float *qf, *kf, *ctx;
    __nv_bfloat16 *vh, *vl;
    cudaGetSymbolAddress((void**)&qf, g_qf);
    cudaGetSymbolAddress((void**)&kf, g_kf);
    cudaGetSymbolAddress((void**)&vh, g_vh);
    cudaGetSymbolAddress((void**)&vl, g_vl);
    cudaGetSymbolAddress((void**)&ctx, g_ctx);

    const float SC2 = 0.18033688011112042f;   // 0.125 * log2(e)

    cudaFuncSetAttribute(gemm_tf32, cudaFuncAttributeMaxDynamicSharedMemorySize,
                         GEMM_SMEM);
    cudaFuncSetAttribute(attn_mma, cudaFuncAttributeMaxDynamicSharedMemorySize,
                         ATTN_SMEM);

    // Fused Q/K/V projections: Q -> fp32 (exp2-scaled), K -> fp32, V -> bf16 hi/lo
    dim3 ggrid(D_ / BN, (B_ * S_) / BM, 3);   // (8, 32, 3)
    gemm_tf32<<<ggrid, 256, GEMM_SMEM>>>(
        query, Wq, bq,
        key,   Wk, bk,
        value, Wv, bv,
        SC2, 1.0f, 1.0f,
        qf, kf, vh, vl);

    // Attention (tf32 QK + bf16 hi/lo PV) -> fp32 ctx
    dim3 agrid(S_ / 128, H_, B_);
    attn_mma<<<agrid, 256, ATTN_SMEM>>>(qf, kf, vh, vl, mask, ctx);

    // Output projection (fp32 out via z==0 path)
    dim3 ogrid(D_ / BN, (B_ * S_) / BM, 1);   // (8, 32, 1)
    gemm_tf32<<<ogrid, 256, GEMM_SMEM>>>(
        ctx, Wo, bo,
        ctx, Wo, bo,
        ctx, Wo, bo,
        1.0f, 1.0f, 1.0f,
        out, nullptr, nullptr, nullptr);
}